// round 15
// baseline (speedup 1.0000x reference)
#include <cuda_runtime.h>
#include <cuda_fp16.h>
#include <mma.h>
#include <math.h>

using namespace nvcuda;

#define BMAX 65536
#define HIS 5
#define KINDS 10

// ---------------------------------------------------------------------------
// Device scratch: all_feat as plain split-fp16 [feature][B] (wmma-loadable).
// Features: 0..39 user/item/age/gender/occ, 40..119 kind, 120..207 pool.
// ---------------------------------------------------------------------------
static __device__ __half g_afh[208u * BMAX];
static __device__ __half g_afl[208u * BMAX];
static __device__ float2 g_base2[32u * BMAX];      // 64 scalar rows fp32
static __device__ float  g_score[HIS * BMAX];

// Tables / prepped weights
static __device__ float  g_Wc0[64 * 8];            // (W1c-W1b)[:,0:8]
static __device__ float  g_Tc[10 * 16 * 20 * 4];   // [j][o4][kk] float4
// Transposed split fp16 weights, [k][n] row-major:
static __device__ __half g_w1th[208 * 128];
static __device__ __half g_w1tl[208 * 128];
static __device__ __half g_w2th[128 * 64];
static __device__ __half g_w2tl[128 * 64];
static __device__ __half g_w3th[64 * 32];
static __device__ __half g_w3tl[64 * 32];

__device__ __forceinline__ float4 ldg4(const float* p) {
    return __ldg((const float4*)p);
}

__device__ __forceinline__ void st_feat1(int B, int b, int f, float x) {
    __half h = __float2half_rn(x);
    g_afh[(size_t)f * (size_t)B + (size_t)b] = h;
    g_afl[(size_t)f * (size_t)B + (size_t)b] = __float2half_rn(x - __half2float(h));
}

__device__ __forceinline__ void st8(int B, int b, int f0, float4 v0, float4 v1) {
    st_feat1(B, b, f0 + 0, v0.x); st_feat1(B, b, f0 + 1, v0.y);
    st_feat1(B, b, f0 + 2, v0.z); st_feat1(B, b, f0 + 3, v0.w);
    st_feat1(B, b, f0 + 4, v1.x); st_feat1(B, b, f0 + 5, v1.y);
    st_feat1(B, b, f0 + 6, v1.z); st_feat1(B, b, f0 + 7, v1.w);
}

// ---------------------------------------------------------------------------
// prep: 512 + 12800 + 26624 + 8192 + 2048 = 50176 outputs.
// ---------------------------------------------------------------------------
extern "C" __global__ void prep_tables(const float* __restrict__ act_w1,
                                       const float* __restrict__ mlp_w1,
                                       const float* __restrict__ mlp_w2,
                                       const float* __restrict__ mlp_w3,
                                       const float* __restrict__ kind_emb)
{
    int i = blockIdx.x * blockDim.x + threadIdx.x;
    if (i < 512) {
        int o = i >> 3, d = i & 7;
        const float* r = act_w1 + o * 264;
        g_Wc0[o * 8 + d] = r[176 + d] - r[88 + d];
        return;
    }
    i -= 512;
    if (i < 12800) {
        int f = i & 3; int r1 = i >> 2;
        int kk = r1 % 20; r1 /= 20;
        int o4 = r1 % 16; int j = r1 / 16;
        int o = 4 * o4 + f;
        float v = 0.f;
        if (kk != 0) {
            const float* r = act_w1 + o * 264 + 8 * (j + 1);
            const float* e = kind_emb + kk * 8;
            #pragma unroll
            for (int d = 0; d < 8; d++)
                v += (r[176 + d] - r[88 + d]) * e[d];
        }
        g_Tc[i] = v;
        return;
    }
    i -= 12800;
    if (i < 26624) {                    // w1t: [k=208][n=128]
        int k = i >> 7, n = i & 127;
        float w = mlp_w1[n * 208 + k];
        __half h = __float2half_rn(w);
        g_w1th[i] = h;
        g_w1tl[i] = __float2half_rn(w - __half2float(h));
        return;
    }
    i -= 26624;
    if (i < 8192) {                     // w2t: [k=128][n=64]
        int k = i >> 6, n = i & 63;
        float w = mlp_w2[n * 128 + k];
        __half h = __float2half_rn(w);
        g_w2th[i] = h;
        g_w2tl[i] = __float2half_rn(w - __half2float(h));
        return;
    }
    i -= 8192;
    if (i < 2048) {                     // w3t: [k=64][n=32]
        int k = i >> 5, n = i & 31;
        float w = mlp_w3[n * 64 + k];
        __half h = __float2half_rn(w);
        g_w3th[i] = h;
        g_w3tl[i] = __float2half_rn(w - __half2float(h));
    }
}

// ---------------------------------------------------------------------------
// k0: gathers -> split fp16 all_feat rows 0..119, base -> g_base2 (fp32).
// ---------------------------------------------------------------------------
extern "C" __global__ void __launch_bounds__(128, 4)
k0_feat(const int* __restrict__ userid, const int* __restrict__ itemid,
        const int* __restrict__ user_age, const int* __restrict__ gender,
        const int* __restrict__ user_occ, const int* __restrict__ item_kind,
        const float* __restrict__ user_emb, const float* __restrict__ item_emb,
        const float* __restrict__ age_emb, const float* __restrict__ gender_emb,
        const float* __restrict__ occ_emb, const float* __restrict__ kind_emb,
        const float* __restrict__ act_b1, int B)
{
    __shared__ float sWc0[64 * 8];
    for (int idx = threadIdx.x; idx < 512; idx += blockDim.x) sWc0[idx] = g_Wc0[idx];
    __syncthreads();

    int b = blockIdx.x * blockDim.x + threadIdx.x;
    if (b >= B) return;
    size_t sB = (size_t)B;

    float4 iv0, iv1;
    {
        const float* p = user_emb + (size_t)userid[b] * 8;
        st8(B, b, 0, ldg4(p), ldg4(p + 4));
        p = item_emb + (size_t)itemid[b] * 8;
        iv0 = ldg4(p); iv1 = ldg4(p + 4);
        st8(B, b, 8, iv0, iv1);
        p = age_emb + (size_t)user_age[b] * 8;
        st8(B, b, 16, ldg4(p), ldg4(p + 4));
        p = gender_emb + (size_t)gender[b] * 8;
        st8(B, b, 24, ldg4(p), ldg4(p + 4));
        p = occ_emb + (size_t)user_occ[b] * 8;
        st8(B, b, 32, ldg4(p), ldg4(p + 4));
    }

    float acc[64];
    #pragma unroll
    for (int o = 0; o < 64; o++) acc[o] = __ldg(act_b1 + o);

    #pragma unroll
    for (int o = 0; o < 64; o++) {
        float4 w0 = *(const float4*)(sWc0 + o * 8);
        float4 w1 = *(const float4*)(sWc0 + o * 8 + 4);
        acc[o] += w0.x*iv0.x + w0.y*iv0.y + w0.z*iv0.z + w0.w*iv0.w
                + w1.x*iv1.x + w1.y*iv1.y + w1.z*iv1.z + w1.w*iv1.w;
    }

    #pragma unroll 1
    for (int j = 0; j < 10; j++) {
        int kk = item_kind[b * KINDS + j];
        const float* p = kind_emb + (size_t)kk * 8;
        float4 v0 = ldg4(p), v1 = ldg4(p + 4);
        if (kk == 0) { v0 = make_float4(0.f,0.f,0.f,0.f); v1 = v0; }
        st8(B, b, 40 + 8 * j, v0, v1);
        const float4* t = (const float4*)g_Tc + (size_t)(j * 16) * 20 + kk;
        #pragma unroll
        for (int o4 = 0; o4 < 16; o4++) {
            float4 v = __ldg(t + o4 * 20);
            acc[4*o4+0] += v.x; acc[4*o4+1] += v.y;
            acc[4*o4+2] += v.z; acc[4*o4+3] += v.w;
        }
    }

    float2* bp = g_base2 + (size_t)b;
    #pragma unroll
    for (int o = 0; o < 32; o++)
        bp[(size_t)o * sB] = make_float2(acc[2*o], acc[2*o + 1]);
}

// ---------------------------------------------------------------------------
// k1s: all 5 attention scores (R11-proven scalar FMA form).
// ---------------------------------------------------------------------------
extern "C" __global__ void __launch_bounds__(128, 4)
k1s_score(const int* __restrict__ his_id, const int* __restrict__ his_kind,
          const float* __restrict__ item_emb, const float* __restrict__ kind_emb,
          const float* __restrict__ act_w1,
          const float* __restrict__ act_w2, const float* __restrict__ act_b2,
          const float* __restrict__ act_w3, const float* __restrict__ act_b3,
          int B)
{
    __shared__ float sWa[64 * 88];
    __shared__ float sW2[32 * 64];
    __shared__ float sB2[32];
    __shared__ float sW3[32];
    __shared__ float sB3s;

    for (int idx = threadIdx.x; idx < 64 * 88; idx += blockDim.x) {
        int o = idx / 88, k = idx - o * 88;
        const float* r = act_w1 + o * 264;
        sWa[idx] = r[k] + r[88 + k];
    }
    for (int idx = threadIdx.x; idx < 32 * 64; idx += blockDim.x) sW2[idx] = act_w2[idx];
    if (threadIdx.x < 32) { sB2[threadIdx.x] = act_b2[threadIdx.x];
                            sW3[threadIdx.x] = act_w3[threadIdx.x]; }
    if (threadIdx.x == 0) sB3s = act_b3[0];
    __syncthreads();

    int b = blockIdx.x * blockDim.x + threadIdx.x;
    if (b >= B) return;
    size_t sB = (size_t)B;

    #pragma unroll 1
    for (int s = 0; s < HIS; s++) {
        float acc[64];
        {
            const float2* bp = g_base2 + (size_t)b;
            #pragma unroll
            for (int o = 0; o < 32; o++) {
                float2 v = bp[(size_t)o * sB];
                acc[2*o] = v.x; acc[2*o + 1] = v.y;
            }
        }

        int hid = his_id[b * HIS + s];
        #pragma unroll 1
        for (int j = 0; j < 11; j++) {
            float4 v0, v1;
            if (j == 0) {
                const float* p = item_emb + (size_t)hid * 8;
                v0 = ldg4(p); v1 = ldg4(p + 4);
            } else {
                int kk = his_kind[(b * HIS + s) * KINDS + (j - 1)];
                const float* p = kind_emb + (size_t)kk * 8;
                v0 = ldg4(p); v1 = ldg4(p + 4);
                float m = (kk != 0) ? 1.f : 0.f;
                v0.x*=m; v0.y*=m; v0.z*=m; v0.w*=m;
                v1.x*=m; v1.y*=m; v1.z*=m; v1.w*=m;
            }
            const float* wb = sWa + j * 8;
            #pragma unroll
            for (int o = 0; o < 64; o++) {
                float4 w0 = *(const float4*)(wb + o * 88);
                float4 w1 = *(const float4*)(wb + o * 88 + 4);
                acc[o] += w0.x*v0.x + w0.y*v0.y + w0.z*v0.z + w0.w*v0.w
                        + w1.x*v1.x + w1.y*v1.y + w1.z*v1.z + w1.w*v1.w;
            }
        }

        float acc2[32];
        #pragma unroll
        for (int o = 0; o < 32; o++) acc2[o] = sB2[o];
        #pragma unroll
        for (int kc = 0; kc < 16; kc++) {
            float a0 = fmaxf(acc[4*kc+0], 0.f);
            float a1 = fmaxf(acc[4*kc+1], 0.f);
            float a2 = fmaxf(acc[4*kc+2], 0.f);
            float a3 = fmaxf(acc[4*kc+3], 0.f);
            const float* wb = sW2 + 4 * kc;
            #pragma unroll
            for (int o = 0; o < 32; o++) {
                float4 w = *(const float4*)(wb + o * 64);
                acc2[o] += w.x*a0 + w.y*a1 + w.z*a2 + w.w*a3;
            }
        }
        float sc = sB3s;
        #pragma unroll
        for (int o = 0; o < 32; o++) sc += sW3[o] * fmaxf(acc2[o], 0.f);
        g_score[(size_t)s * sB + (size_t)b] = sc;
    }
}

// ---------------------------------------------------------------------------
// k2: his_pool -> split fp16 features 120..207.
// ---------------------------------------------------------------------------
extern "C" __global__ void __launch_bounds__(128, 4)
k2_pool(const int* __restrict__ his_id, const int* __restrict__ his_kind,
        const float* __restrict__ item_emb, const float* __restrict__ kind_emb,
        int B)
{
    int b = blockIdx.x * blockDim.x + threadIdx.x;
    if (b >= B) return;
    size_t sB = (size_t)B;

    float poolL[88];
    #pragma unroll
    for (int d = 0; d < 88; d++) poolL[d] = 0.f;

    #pragma unroll 1
    for (int s = 0; s < HIS; s++) {
        float sc = g_score[(size_t)s * sB + (size_t)b];
        int hid = his_id[b * HIS + s];
        {
            const float* p = item_emb + (size_t)hid * 8;
            float4 v0 = ldg4(p), v1 = ldg4(p + 4);
            poolL[0] += v0.x*v0.x*sc; poolL[1] += v0.y*v0.y*sc;
            poolL[2] += v0.z*v0.z*sc; poolL[3] += v0.w*v0.w*sc;
            poolL[4] += v1.x*v1.x*sc; poolL[5] += v1.y*v1.y*sc;
            poolL[6] += v1.z*v1.z*sc; poolL[7] += v1.w*v1.w*sc;
        }
        #pragma unroll
        for (int j = 0; j < 10; j++) {
            int kk = his_kind[(b * HIS + s) * KINDS + j];
            const float* p = kind_emb + (size_t)kk * 8;
            float4 v0 = ldg4(p), v1 = ldg4(p + 4);
            float fm = (kk != 0) ? sc : 0.f;
            int pp = 8 + j * 8;
            poolL[pp+0] += v0.x*v0.x*fm; poolL[pp+1] += v0.y*v0.y*fm;
            poolL[pp+2] += v0.z*v0.z*fm; poolL[pp+3] += v0.w*v0.w*fm;
            poolL[pp+4] += v1.x*v1.x*fm; poolL[pp+5] += v1.y*v1.y*fm;
            poolL[pp+6] += v1.z*v1.z*fm; poolL[pp+7] += v1.w*v1.w*fm;
        }
    }
    #pragma unroll 1
    for (int d = 0; d < 88; d++)
        st_feat1(B, b, 120 + d, poolL[d]);
}

// ---------------------------------------------------------------------------
// t2_mlp v2: fused 208->128->64->32->1 + sigmoid, split-fp16 wmma with
// A and B fragments loaded DIRECTLY from global (no staging, no k-tile syncs).
// ---------------------------------------------------------------------------
#define T2_SMEM 139776

extern "C" __global__ void __launch_bounds__(512, 1)
t2_mlp(const float* __restrict__ mlp_b1, const float* __restrict__ mlp_b2,
       const float* __restrict__ mlp_b3, const float* __restrict__ mlp_w4,
       const float* __restrict__ mlp_b4, float* __restrict__ out, int B)
{
    extern __shared__ char smem[];
    __half* sA2H = (__half*)(smem + 0);        // [128][136]
    __half* sA2L = (__half*)(smem + 34816);
    __half* sA3H = (__half*)(smem + 69632);    // [128][72]
    __half* sA3L = (__half*)(smem + 88064);
    float*  sScr = (float*)(smem + 106496);    // [16][256]
    float*  sH3  = (float*)(smem + 122880);    // [128][33]

    int tid = threadIdx.x;
    int w = tid >> 5, lane = tid & 31;
    int m0 = blockIdx.x * 128;
    int mr = w >> 1;
    int m0w = mr * 16;
    float* scr = sScr + w * 256;
    size_t sB = (size_t)B;

    typedef wmma::fragment<wmma::matrix_a, 16,16,16, __half, wmma::col_major> FragAc;
    typedef wmma::fragment<wmma::matrix_a, 16,16,16, __half, wmma::row_major> FragAr;
    typedef wmma::fragment<wmma::matrix_b, 16,16,16, __half, wmma::row_major> FragB;
    typedef wmma::fragment<wmma::accumulator, 16,16,16, float> FragC;

    // ===== Layer 1: A frags from g_af (col-major, ldm=B), B frags from g_w1t =====
    FragC acc[4];
    #pragma unroll
    for (int c = 0; c < 4; c++) wmma::fill_fragment(acc[c], 0.0f);
    int nb1 = (w & 1) * 4;

    #pragma unroll 1
    for (int t = 0; t < 13; t++) {
        FragAc ah, al;
        wmma::load_matrix_sync(ah, g_afh + (size_t)(16*t) * sB + (size_t)(m0 + m0w), B);
        wmma::load_matrix_sync(al, g_afl + (size_t)(16*t) * sB + (size_t)(m0 + m0w), B);
        #pragma unroll
        for (int c = 0; c < 4; c++) {
            int n0 = (nb1 + c) * 16;
            FragB bh, bl;
            wmma::load_matrix_sync(bh, g_w1th + (16*t) * 128 + n0, 128);
            wmma::load_matrix_sync(bl, g_w1tl + (16*t) * 128 + n0, 128);
            wmma::mma_sync(acc[c], ah, bh, acc[c]);
            wmma::mma_sync(acc[c], ah, bl, acc[c]);
            wmma::mma_sync(acc[c], al, bh, acc[c]);
        }
    }
    // epilogue L1: bias + relu + split -> sA2
    #pragma unroll 1
    for (int c = 0; c < 4; c++) {
        __syncwarp();
        wmma::store_matrix_sync(scr, acc[c], 16, wmma::mem_row_major);
        __syncwarp();
        int n0 = (nb1 + c) * 16;
        #pragma unroll
        for (int i = 0; i < 8; i++) {
            int idx = i * 32 + lane;
            int r = idx >> 4, cc = idx & 15;
            int n = n0 + cc, m = m0w + r;
            float v = scr[idx] + __ldg(mlp_b1 + n);
            v = fmaxf(v, 0.f);
            __half hv = __float2half_rn(v);
            sA2H[m * 136 + n] = hv;
            sA2L[m * 136 + n] = __float2half_rn(v - __half2float(hv));
        }
    }
    __syncthreads();

    // ===== Layer 2: A from sA2 (smem), B frags from g_w2t (ldm=64) =====
    FragC acc2[2];
    #pragma unroll
    for (int c = 0; c < 2; c++) wmma::fill_fragment(acc2[c], 0.0f);
    int nb2 = (w & 1) * 2;

    #pragma unroll 1
    for (int t = 0; t < 8; t++) {
        FragAr ah, al;
        wmma::load_matrix_sync(ah, sA2H + m0w * 136 + 16 * t, 136);
        wmma::load_matrix_sync(al, sA2L + m0w * 136 + 16 * t, 136);
        #pragma unroll
        for (int c = 0; c < 2; c++) {
            int n0 = (nb2 + c) * 16;
            FragB bh, bl;
            wmma::load_matrix_sync(bh, g_w2th + (16*t) * 64 + n0, 64);
            wmma::load_matrix_sync(bl, g_w2tl + (16*t) * 64 + n0, 64);
            wmma::mma_sync(acc2[c], ah, bh, acc2[c]);
            wmma::mma_sync(acc2[c], ah, bl, acc2[c]);
            wmma::mma_sync(acc2[c], al, bh, acc2[c]);
        }
    }
    #pragma unroll 1
    for (int c = 0; c < 2; c++) {
        __syncwarp();
        wmma::store_matrix_sync(scr, acc2[c], 16, wmma::mem_row_major);
        __syncwarp();
        int n0 = (nb2 + c) * 16;
        #pragma unroll
        for (int i = 0; i < 8; i++) {
            int idx = i * 32 + lane;
            int r = idx >> 4, cc = idx & 15;
            int n = n0 + cc, m = m0w + r;
            float v = scr[idx] + __ldg(mlp_b2 + n);
            v = fmaxf(v, 0.f);
            __half hv = __float2half_rn(v);
            sA3H[m * 72 + n] = hv;
            sA3L[m * 72 + n] = __float2half_rn(v - __half2float(hv));
        }
    }
    __syncthreads();

    // ===== Layer 3: A from sA3, B frags from g_w3t (ldm=32) =====
    FragC acc3;
    wmma::fill_fragment(acc3, 0.0f);
    int n03 = (w & 1) * 16;

    #pragma unroll 1
    for (int t = 0; t < 4; t++) {
        FragAr ah, al;
        wmma::load_matrix_sync(ah, sA3H + m0w * 72 + 16 * t, 72);
        wmma::load_matrix_sync(al, sA3L + m0w * 72 + 16 * t, 72);
        FragB bh, bl;
        wmma::load_matrix_sync(bh, g_w3th + (16*t) * 32 + n03, 32);
        wmma::load_matrix_sync(bl, g_w3tl + (16*t) * 32 + n03, 32);
        wmma::mma_sync(acc3, ah, bh, acc3);
        wmma::mma_sync(acc3, ah, bl, acc3);
        wmma::mma_sync(acc3, al, bh, acc3);
    }
    __syncwarp();
    wmma::store_matrix_sync(scr, acc3, 16, wmma::mem_row_major);
    __syncwarp();
    #pragma unroll
    for (int i = 0; i < 8; i++) {
        int idx = i * 32 + lane;
        int r = idx >> 4, cc = idx & 15;
        int n = n03 + cc, m = m0w + r;
        float v = scr[idx] + __ldg(mlp_b3 + n);
        sH3[m * 33 + n] = fmaxf(v, 0.f);
    }
    __syncthreads();

    // ===== Layer 4 + sigmoid =====
    if (tid < 128) {
        int m = tid;
        float logit = __ldg(mlp_b4);
        #pragma unroll
        for (int o = 0; o < 32; o++)
            logit += __ldg(mlp_w4 + o) * sH3[m * 33 + o];
        out[m0 + m] = 1.f / (1.f + expf(-logit));
    }
}

// ---------------------------------------------------------------------------
extern "C" void kernel_launch(void* const* d_in, const int* in_sizes, int n_in,
                              void* d_out, int out_size)
{
    const int*   userid   = (const int*)d_in[0];
    const int*   itemid   = (const int*)d_in[1];
    const int*   user_age = (const int*)d_in[2];
    const int*   gender   = (const int*)d_in[3];
    const int*   user_occ = (const int*)d_in[4];
    const int*   item_kind= (const int*)d_in[5];
    const int*   his_id   = (const int*)d_in[6];
    const int*   his_kind = (const int*)d_in[7];
    const float* user_emb = (const float*)d_in[8];
    const float* item_emb = (const float*)d_in[9];
    const float* age_emb  = (const float*)d_in[10];
    const float* gen_emb  = (const float*)d_in[11];
    const float* occ_emb  = (const float*)d_in[12];
    const float* kind_emb = (const float*)d_in[13];
    const float* act_w1 = (const float*)d_in[14];
    const float* act_b1 = (const float*)d_in[15];
    const float* act_w2 = (const float*)d_in[16];
    const float* act_b2 = (const float*)d_in[17];
    const float* act_w3 = (const float*)d_in[18];
    const float* act_b3 = (const float*)d_in[19];
    const float* mlp_w1 = (const float*)d_in[20];
    const float* mlp_b1 = (const float*)d_in[21];
    const float* mlp_w2 = (const float*)d_in[22];
    const float* mlp_b2 = (const float*)d_in[23];
    const float* mlp_w3 = (const float*)d_in[24];
    const float* mlp_b3 = (const float*)d_in[25];
    const float* mlp_w4 = (const float*)d_in[26];
    const float* mlp_b4 = (const float*)d_in[27];

    int B = in_sizes[0];
    int nb = (B + 127) / 128;

    cudaFuncSetAttribute((const void*)t2_mlp,
                         cudaFuncAttributeMaxDynamicSharedMemorySize, T2_SMEM);

    prep_tables<<<196, 256>>>(act_w1, mlp_w1, mlp_w2, mlp_w3, kind_emb);

    k0_feat<<<nb, 128>>>(userid, itemid, user_age, gender, user_occ, item_kind,
                         user_emb, item_emb, age_emb, gen_emb, occ_emb, kind_emb,
                         act_b1, B);

    k1s_score<<<nb, 128>>>(his_id, his_kind, item_emb, kind_emb, act_w1,
                           act_w2, act_b2, act_w3, act_b3, B);

    k2_pool<<<nb, 128>>>(his_id, his_kind, item_emb, kind_emb, B);

    t2_mlp<<<nb, 512, T2_SMEM>>>(mlp_b1, mlp_b2, mlp_b3, mlp_w4, mlp_b4,
                                 (float*)d_out, B);
}

// round 16
// speedup vs baseline: 1.7767x; 1.7767x over previous
#include <cuda_runtime.h>
#include <cuda_fp16.h>
#include <mma.h>
#include <math.h>

using namespace nvcuda;

#define BMAX 65536
#define HIS 5
#define KINDS 10

// ---------------------------------------------------------------------------
// Device scratch (R11 layout: half2 pair-packed transposed all_feat)
// ---------------------------------------------------------------------------
static __device__ __half2 g_af2h[104u * BMAX];
static __device__ __half2 g_af2l[104u * BMAX];
static __device__ float2  g_base2[32u * BMAX];     // 64 scalar rows fp32
static __device__ float   g_score[HIS * BMAX];

// Tables / prepped weights
static __device__ float  g_Wc0[64 * 8];            // (W1c-W1b)[:,0:8]
static __device__ float  g_Tc[10 * 16 * 20 * 4];   // [j][o4][kk] float4 (Wc@kind)
static __device__ float  g_Ta[10 * 16 * 20 * 4];   // [j][o4][kk] float4 (Wa@kind)
// Transposed split fp16 weights, [k][n] row-major:
static __device__ __half g_w1th[208 * 128];
static __device__ __half g_w1tl[208 * 128];
static __device__ __half g_w2th[128 * 64];
static __device__ __half g_w2tl[128 * 64];
static __device__ __half g_w3th[64 * 32];
static __device__ __half g_w3tl[64 * 32];

__device__ __forceinline__ float4 ldg4(const float* p) {
    return __ldg((const float4*)p);
}

__device__ __forceinline__ void st_feat(int B, int b, int rp, float x, float y) {
    __half hx = __float2half_rn(x), hy = __float2half_rn(y);
    float lx = x - __half2float(hx), ly = y - __half2float(hy);
    g_af2h[(size_t)rp * (size_t)B + (size_t)b] = __halves2half2(hx, hy);
    g_af2l[(size_t)rp * (size_t)B + (size_t)b] =
        __halves2half2(__float2half_rn(lx), __float2half_rn(ly));
}

__device__ __forceinline__ void st8(int B, int b, int rp, float4 v0, float4 v1) {
    st_feat(B, b, rp + 0, v0.x, v0.y);
    st_feat(B, b, rp + 1, v0.z, v0.w);
    st_feat(B, b, rp + 2, v1.x, v1.y);
    st_feat(B, b, rp + 3, v1.z, v1.w);
}

// ---------------------------------------------------------------------------
// prep: 512 + 12800 (Tc) + 12800 (Ta) + 26624 + 8192 + 2048 = 62976 outputs.
// ---------------------------------------------------------------------------
extern "C" __global__ void prep_tables(const float* __restrict__ act_w1,
                                       const float* __restrict__ mlp_w1,
                                       const float* __restrict__ mlp_w2,
                                       const float* __restrict__ mlp_w3,
                                       const float* __restrict__ kind_emb)
{
    int i = blockIdx.x * blockDim.x + threadIdx.x;
    if (i < 512) {
        int o = i >> 3, d = i & 7;
        const float* r = act_w1 + o * 264;
        g_Wc0[o * 8 + d] = r[176 + d] - r[88 + d];
        return;
    }
    i -= 512;
    if (i < 25600) {                    // Tc then Ta, same [j][o4][kk] layout
        int which = i >= 12800;         // 0 = Tc, 1 = Ta
        int t = which ? i - 12800 : i;
        int f = t & 3; int r1 = t >> 2;
        int kk = r1 % 20; r1 /= 20;
        int o4 = r1 % 16; int j = r1 / 16;
        int o = 4 * o4 + f;
        float v = 0.f;
        if (kk != 0) {
            const float* r = act_w1 + o * 264 + 8 * (j + 1);
            const float* e = kind_emb + kk * 8;
            #pragma unroll
            for (int d = 0; d < 8; d++) {
                float w = which ? (r[d] + r[88 + d]) : (r[176 + d] - r[88 + d]);
                v += w * e[d];
            }
        }
        if (which) g_Ta[t] = v;
        else       g_Tc[t] = v;
        return;
    }
    i -= 25600;
    if (i < 26624) {                    // w1t: [k=208][n=128]
        int k = i >> 7, n = i & 127;
        float w = mlp_w1[n * 208 + k];
        __half h = __float2half_rn(w);
        g_w1th[i] = h;
        g_w1tl[i] = __float2half_rn(w - __half2float(h));
        return;
    }
    i -= 26624;
    if (i < 8192) {                     // w2t: [k=128][n=64]
        int k = i >> 6, n = i & 63;
        float w = mlp_w2[n * 128 + k];
        __half h = __float2half_rn(w);
        g_w2th[i] = h;
        g_w2tl[i] = __float2half_rn(w - __half2float(h));
        return;
    }
    i -= 8192;
    if (i < 2048) {                     // w3t: [k=64][n=32]
        int k = i >> 5, n = i & 31;
        float w = mlp_w3[n * 64 + k];
        __half h = __float2half_rn(w);
        g_w3th[i] = h;
        g_w3tl[i] = __float2half_rn(w - __half2float(h));
    }
}

// ---------------------------------------------------------------------------
// k0: gathers -> split fp16 all_feat rows 0..119, base -> g_base2 (fp32).
// (R11-proven, unchanged)
// ---------------------------------------------------------------------------
extern "C" __global__ void __launch_bounds__(128, 4)
k0_feat(const int* __restrict__ userid, const int* __restrict__ itemid,
        const int* __restrict__ user_age, const int* __restrict__ gender,
        const int* __restrict__ user_occ, const int* __restrict__ item_kind,
        const float* __restrict__ user_emb, const float* __restrict__ item_emb,
        const float* __restrict__ age_emb, const float* __restrict__ gender_emb,
        const float* __restrict__ occ_emb, const float* __restrict__ kind_emb,
        const float* __restrict__ act_b1, int B)
{
    __shared__ float sWc0[64 * 8];
    for (int idx = threadIdx.x; idx < 512; idx += blockDim.x) sWc0[idx] = g_Wc0[idx];
    __syncthreads();

    int b = blockIdx.x * blockDim.x + threadIdx.x;
    if (b >= B) return;
    size_t sB = (size_t)B;

    float4 iv0, iv1;
    {
        const float* p = user_emb + (size_t)userid[b] * 8;
        st8(B, b, 0, ldg4(p), ldg4(p + 4));
        p = item_emb + (size_t)itemid[b] * 8;
        iv0 = ldg4(p); iv1 = ldg4(p + 4);
        st8(B, b, 4, iv0, iv1);
        p = age_emb + (size_t)user_age[b] * 8;
        st8(B, b, 8, ldg4(p), ldg4(p + 4));
        p = gender_emb + (size_t)gender[b] * 8;
        st8(B, b, 12, ldg4(p), ldg4(p + 4));
        p = occ_emb + (size_t)user_occ[b] * 8;
        st8(B, b, 16, ldg4(p), ldg4(p + 4));
    }

    float acc[64];
    #pragma unroll
    for (int o = 0; o < 64; o++) acc[o] = __ldg(act_b1 + o);

    #pragma unroll
    for (int o = 0; o < 64; o++) {
        float4 w0 = *(const float4*)(sWc0 + o * 8);
        float4 w1 = *(const float4*)(sWc0 + o * 8 + 4);
        acc[o] += w0.x*iv0.x + w0.y*iv0.y + w0.z*iv0.z + w0.w*iv0.w
                + w1.x*iv1.x + w1.y*iv1.y + w1.z*iv1.z + w1.w*iv1.w;
    }

    #pragma unroll 1
    for (int j = 0; j < 10; j++) {
        int kk = item_kind[b * KINDS + j];
        const float* p = kind_emb + (size_t)kk * 8;
        float4 v0 = ldg4(p), v1 = ldg4(p + 4);
        if (kk == 0) { v0 = make_float4(0.f,0.f,0.f,0.f); v1 = v0; }
        st8(B, b, 20 + 4 * j, v0, v1);
        const float4* t = (const float4*)g_Tc + (size_t)(j * 16) * 20 + kk;
        #pragma unroll
        for (int o4 = 0; o4 < 16; o4++) {
            float4 v = __ldg(t + o4 * 20);
            acc[4*o4+0] += v.x; acc[4*o4+1] += v.y;
            acc[4*o4+2] += v.z; acc[4*o4+3] += v.w;
        }
    }

    float2* bp = g_base2 + (size_t)b;
    #pragma unroll
    for (int o = 0; o < 32; o++)
        bp[(size_t)o * sB] = make_float2(acc[2*o], acc[2*o + 1]);
}

// ---------------------------------------------------------------------------
// k1s: all 5 attention scores. Kind chunks via g_Ta table ([j][o4][kk] float4,
// the gather-friendly layout proven in k0). Item chunk via tiny smem FMA.
// ---------------------------------------------------------------------------
extern "C" __global__ void __launch_bounds__(128, 4)
k1s_score(const int* __restrict__ his_id, const int* __restrict__ his_kind,
          const float* __restrict__ item_emb,
          const float* __restrict__ act_w1,
          const float* __restrict__ act_w2, const float* __restrict__ act_b2,
          const float* __restrict__ act_w3, const float* __restrict__ act_b3,
          int B)
{
    __shared__ float sWa0[64 * 8];   // (W1a+W1b)[:,0:8]
    __shared__ float sW2[32 * 64];
    __shared__ float sB2[32];
    __shared__ float sW3[32];
    __shared__ float sB3s;

    for (int idx = threadIdx.x; idx < 512; idx += blockDim.x) {
        int o = idx >> 3, d = idx & 7;
        const float* r = act_w1 + o * 264;
        sWa0[idx] = r[d] + r[88 + d];
    }
    for (int idx = threadIdx.x; idx < 32 * 64; idx += blockDim.x) sW2[idx] = act_w2[idx];
    if (threadIdx.x < 32) { sB2[threadIdx.x] = act_b2[threadIdx.x];
                            sW3[threadIdx.x] = act_w3[threadIdx.x]; }
    if (threadIdx.x == 0) sB3s = act_b3[0];
    __syncthreads();

    int b = blockIdx.x * blockDim.x + threadIdx.x;
    if (b >= B) return;
    size_t sB = (size_t)B;

    #pragma unroll 1
    for (int s = 0; s < HIS; s++) {
        float acc[64];
        {
            const float2* bp = g_base2 + (size_t)b;
            #pragma unroll
            for (int o = 0; o < 32; o++) {
                float2 v = bp[(size_t)o * sB];
                acc[2*o] = v.x; acc[2*o + 1] = v.y;
            }
        }

        // item chunk (dense 8-dim FMA, weights in smem)
        {
            int hid = his_id[b * HIS + s];
            const float* p = item_emb + (size_t)hid * 8;
            float4 v0 = ldg4(p), v1 = ldg4(p + 4);
            #pragma unroll
            for (int o = 0; o < 64; o++) {
                float4 w0 = *(const float4*)(sWa0 + o * 8);
                float4 w1 = *(const float4*)(sWa0 + o * 8 + 4);
                acc[o] += w0.x*v0.x + w0.y*v0.y + w0.z*v0.z + w0.w*v0.w
                        + w1.x*v1.x + w1.y*v1.y + w1.z*v1.z + w1.w*v1.w;
            }
        }

        // kind chunks via precomputed table (kk==0 rows are zero)
        #pragma unroll 1
        for (int j = 0; j < 10; j++) {
            int kk = his_kind[(b * HIS + s) * KINDS + j];
            const float4* t = (const float4*)g_Ta + (size_t)(j * 16) * 20 + kk;
            #pragma unroll
            for (int o4 = 0; o4 < 16; o4++) {
                float4 v = __ldg(t + o4 * 20);
                acc[4*o4+0] += v.x; acc[4*o4+1] += v.y;
                acc[4*o4+2] += v.z; acc[4*o4+3] += v.w;
            }
        }

        // layer 2, fully unrolled (h1 stays in registers)
        float acc2[32];
        #pragma unroll
        for (int o = 0; o < 32; o++) acc2[o] = sB2[o];
        #pragma unroll
        for (int kc = 0; kc < 16; kc++) {
            float a0 = fmaxf(acc[4*kc+0], 0.f);
            float a1 = fmaxf(acc[4*kc+1], 0.f);
            float a2 = fmaxf(acc[4*kc+2], 0.f);
            float a3 = fmaxf(acc[4*kc+3], 0.f);
            const float* wb = sW2 + 4 * kc;
            #pragma unroll
            for (int o = 0; o < 32; o++) {
                float4 w = *(const float4*)(wb + o * 64);
                acc2[o] += w.x*a0 + w.y*a1 + w.z*a2 + w.w*a3;
            }
        }
        float sc = sB3s;
        #pragma unroll
        for (int o = 0; o < 32; o++) sc += sW3[o] * fmaxf(acc2[o], 0.f);
        g_score[(size_t)s * sB + (size_t)b] = sc;
    }
}

// ---------------------------------------------------------------------------
// k2: his_pool -> split fp16 rows 120..207 (rowpairs 60..103). (R11-proven)
// ---------------------------------------------------------------------------
extern "C" __global__ void __launch_bounds__(128, 4)
k2_pool(const int* __restrict__ his_id, const int* __restrict__ his_kind,
        const float* __restrict__ item_emb, const float* __restrict__ kind_emb,
        int B)
{
    int b = blockIdx.x * blockDim.x + threadIdx.x;
    if (b >= B) return;
    size_t sB = (size_t)B;

    float poolL[88];
    #pragma unroll
    for (int d = 0; d < 88; d++) poolL[d] = 0.f;

    #pragma unroll 1
    for (int s = 0; s < HIS; s++) {
        float sc = g_score[(size_t)s * sB + (size_t)b];
        int hid = his_id[b * HIS + s];
        {
            const float* p = item_emb + (size_t)hid * 8;
            float4 v0 = ldg4(p), v1 = ldg4(p + 4);
            poolL[0] += v0.x*v0.x*sc; poolL[1] += v0.y*v0.y*sc;
            poolL[2] += v0.z*v0.z*sc; poolL[3] += v0.w*v0.w*sc;
            poolL[4] += v1.x*v1.x*sc; poolL[5] += v1.y*v1.y*sc;
            poolL[6] += v1.z*v1.z*sc; poolL[7] += v1.w*v1.w*sc;
        }
        #pragma unroll
        for (int j = 0; j < 10; j++) {
            int kk = his_kind[(b * HIS + s) * KINDS + j];
            const float* p = kind_emb + (size_t)kk * 8;
            float4 v0 = ldg4(p), v1 = ldg4(p + 4);
            float fm = (kk != 0) ? sc : 0.f;
            int pp = 8 + j * 8;
            poolL[pp+0] += v0.x*v0.x*fm; poolL[pp+1] += v0.y*v0.y*fm;
            poolL[pp+2] += v0.z*v0.z*fm; poolL[pp+3] += v0.w*v0.w*fm;
            poolL[pp+4] += v1.x*v1.x*fm; poolL[pp+5] += v1.y*v1.y*fm;
            poolL[pp+6] += v1.z*v1.z*fm; poolL[pp+7] += v1.w*v1.w*fm;
        }
    }
    #pragma unroll 1
    for (int d = 0; d < 44; d++)
        st_feat(B, b, 60 + d, poolL[2*d], poolL[2*d + 1]);
}

// ---------------------------------------------------------------------------
// t2_mlp: fused 208->128->64->32->1 + sigmoid via split-fp16 wmma.
// R11 structure; w2/w3 staged ONCE upfront (kills 24 per-tile barriers).
// ---------------------------------------------------------------------------
#define T2_SMEM 204288

extern "C" __global__ void __launch_bounds__(512, 1)
t2_mlp(const float* __restrict__ mlp_b1, const float* __restrict__ mlp_b2,
       const float* __restrict__ mlp_b3, const float* __restrict__ mlp_w4,
       const float* __restrict__ mlp_b4, float* __restrict__ out, int B)
{
    extern __shared__ char smem[];
    __half* sAkH = (__half*)(smem + 0);        // [16][136]
    __half* sAkL = (__half*)(smem + 4352);
    __half* sBkH = (__half*)(smem + 8704);     // [16][136]
    __half* sBkL = (__half*)(smem + 13056);
    __half* sA2H = (__half*)(smem + 17408);    // [128][136]
    __half* sA2L = (__half*)(smem + 52224);
    __half* sA3H = (__half*)(smem + 87040);    // [128][72]
    __half* sA3L = (__half*)(smem + 105472);
    float*  sScr = (float*)(smem + 123904);    // [16][256]
    float*  sH3  = (float*)(smem + 140288);    // [128][33]
    __half* sW2fH = (__half*)(smem + 157184);  // [128][72]
    __half* sW2fL = (__half*)(smem + 175616);
    __half* sW3fH = (__half*)(smem + 194048);  // [64][40]
    __half* sW3fL = (__half*)(smem + 199168);

    int tid = threadIdx.x;
    int w = tid >> 5, lane = tid & 31;
    int m0 = blockIdx.x * 128;
    int mr = w >> 1;
    int m0w = mr * 16;
    float* scr = sScr + w * 256;

    typedef wmma::fragment<wmma::matrix_a, 16,16,16, __half, wmma::col_major> FragAc;
    typedef wmma::fragment<wmma::matrix_a, 16,16,16, __half, wmma::row_major> FragAr;
    typedef wmma::fragment<wmma::matrix_b, 16,16,16, __half, wmma::row_major> FragB;
    typedef wmma::fragment<wmma::accumulator, 16,16,16, float> FragC;

    // stage w2/w3 upfront (coalesced half2; visibility covered by loop syncs)
    for (int i = tid; i < 4096; i += 512) {        // w2: [k=128][n2=32]
        int k = i >> 5, n2 = i & 31;
        ((__half2*)sW2fH)[k * 36 + n2] = ((const __half2*)g_w2th)[i];
        ((__half2*)sW2fL)[k * 36 + n2] = ((const __half2*)g_w2tl)[i];
    }
    for (int i = tid; i < 1024; i += 512) {        // w3: [k=64][n2=16]
        int k = i >> 4, n2 = i & 15;
        ((__half2*)sW3fH)[k * 20 + n2] = ((const __half2*)g_w3th)[i];
        ((__half2*)sW3fL)[k * 20 + n2] = ((const __half2*)g_w3tl)[i];
    }

    // ================= Layer 1 =================
    FragC acc[4];
    #pragma unroll
    for (int c = 0; c < 4; c++) wmma::fill_fragment(acc[c], 0.0f);
    int nb1 = (w & 1) * 4;

    #pragma unroll 1
    for (int t = 0; t < 13; t++) {
        __syncthreads();
        #pragma unroll
        for (int i = tid; i < 1024; i += 512) {
            int j = i >> 7, m = i & 127;
            size_t src = (size_t)(8 * t + j) * (size_t)B + (size_t)(m0 + m);
            __half2 vh = g_af2h[src];
            __half2 vl = g_af2l[src];
            sAkH[(2*j) * 136 + m]     = __low2half(vh);
            sAkH[(2*j + 1) * 136 + m] = __high2half(vh);
            sAkL[(2*j) * 136 + m]     = __low2half(vl);
            sAkL[(2*j + 1) * 136 + m] = __high2half(vl);
        }
        #pragma unroll
        for (int i = tid; i < 1024; i += 512) {
            int kk = i >> 6, c2 = i & 63;
            *(__half2*)&sBkH[kk * 136 + 2 * c2] =
                ((const __half2*)g_w1th)[(16 * t + kk) * 64 + c2];
            *(__half2*)&sBkL[kk * 136 + 2 * c2] =
                ((const __half2*)g_w1tl)[(16 * t + kk) * 64 + c2];
        }
        __syncthreads();

        FragAc ah, al;
        wmma::load_matrix_sync(ah, sAkH + m0w, 136);
        wmma::load_matrix_sync(al, sAkL + m0w, 136);
        #pragma unroll
        for (int c = 0; c < 4; c++) {
            int n0 = (nb1 + c) * 16;
            FragB bh, bl;
            wmma::load_matrix_sync(bh, sBkH + n0, 136);
            wmma::load_matrix_sync(bl, sBkL + n0, 136);
            wmma::mma_sync(acc[c], ah, bh, acc[c]);
            wmma::mma_sync(acc[c], ah, bl, acc[c]);
            wmma::mma_sync(acc[c], al, bh, acc[c]);
        }
    }
    #pragma unroll 1
    for (int c = 0; c < 4; c++) {
        __syncwarp();
        wmma::store_matrix_sync(scr, acc[c], 16, wmma::mem_row_major);
        __syncwarp();
        int n0 = (nb1 + c) * 16;
        #pragma unroll
        for (int i = 0; i < 8; i++) {
            int idx = i * 32 + lane;
            int r = idx >> 4, cc = idx & 15;
            int n = n0 + cc, m = m0w + r;
            float v = scr[idx] + __ldg(mlp_b1 + n);
            v = fmaxf(v, 0.f);
            __half hv = __float2half_rn(v);
            sA2H[m * 136 + n] = hv;
            sA2L[m * 136 + n] = __float2half_rn(v - __half2float(hv));
        }
    }
    __syncthreads();

    // ================= Layer 2 (B from smem-resident sW2f, no k-tile syncs) ==
    FragC acc2[2];
    #pragma unroll
    for (int c = 0; c < 2; c++) wmma::fill_fragment(acc2[c], 0.0f);
    int nb2 = (w & 1) * 2;

    #pragma unroll 1
    for (int t = 0; t < 8; t++) {
        FragAr ah, al;
        wmma::load_matrix_sync(ah, sA2H + m0w * 136 + 16 * t, 136);
        wmma::load_matrix_sync(al, sA2L + m0w * 136 + 16 * t, 136);
        #pragma unroll
        for (int c = 0; c < 2; c++) {
            int n0 = (nb2 + c) * 16;
            FragB bh, bl;
            wmma::load_matrix_sync(bh, sW2fH + (16*t) * 72 + n0, 72);
            wmma::load_matrix_sync(bl, sW2fL + (16*t) * 72 + n0, 72);
            wmma::mma_sync(acc2[c], ah, bh, acc2[c]);
            wmma::mma_sync(acc2[c], ah, bl, acc2[c]);
            wmma::mma_sync(acc2[c], al, bh, acc2[c]);
        }
    }
    #pragma unroll 1
    for (int c = 0; c < 2; c++) {
        __syncwarp();
        wmma::store_matrix_sync(scr, acc2[c], 16, wmma::mem_row_major);
        __syncwarp();
        int n0 = (nb2 + c) * 16;
        #pragma unroll
        for (int i = 0; i < 8; i++) {
            int idx = i * 32 + lane;
            int r = idx >> 4, cc = idx & 15;
            int n = n0 + cc, m = m0w + r;
            float v = scr[idx] + __ldg(mlp_b2 + n);
            v = fmaxf(v, 0.f);
            __half hv = __float2half_rn(v);
            sA3H[m * 72 + n] = hv;
            sA3L[m * 72 + n] = __float2half_rn(v - __half2float(hv));
        }
    }
    __syncthreads();

    // ================= Layer 3 (B from smem-resident sW3f) =================
    FragC acc3;
    wmma::fill_fragment(acc3, 0.0f);
    int n03 = (w & 1) * 16;

    #pragma unroll 1
    for (int t = 0; t < 4; t++) {
        FragAr ah, al;
        wmma::load_matrix_sync(ah, sA3H + m0w * 72 + 16 * t, 72);
        wmma::load_matrix_sync(al, sA3L + m0w * 72 + 16 * t, 72);
        FragB bh, bl;
        wmma::load_matrix_sync(bh, sW3fH + (16*t) * 40 + n03, 40);
        wmma::load_matrix_sync(bl, sW3fL + (16*t) * 40 + n03, 40);
        wmma::mma_sync(acc3, ah, bh, acc3);
        wmma::mma_sync(acc3, ah, bl, acc3);
        wmma::mma_sync(acc3, al, bh, acc3);
    }
    __syncwarp();
    wmma::store_matrix_sync(scr, acc3, 16, wmma::mem_row_major);
    __syncwarp();
    #pragma unroll
    for (int i = 0; i < 8; i++) {
        int idx = i * 32 + lane;
        int r = idx >> 4, cc = idx & 15;
        int n = n03 + cc, m = m0w + r;
        float v = scr[idx] + __ldg(mlp_b3 + n);
        sH3[m * 33 + n] = fmaxf(v, 0.f);
    }
    __syncthreads();

    // ================= Layer 4 + sigmoid =================
    if (tid < 128) {
        int m = tid;
        float logit = __ldg(mlp_b4);
        #pragma unroll
        for (int o = 0; o < 32; o++)
            logit += __ldg(mlp_w4 + o) * sH3[m * 33 + o];
        out[m0 + m] = 1.f / (1.f + expf(-logit));
    }
}

// ---------------------------------------------------------------------------
extern "C" void kernel_launch(void* const* d_in, const int* in_sizes, int n_in,
                              void* d_out, int out_size)
{
    const int*   userid   = (const int*)d_in[0];
    const int*   itemid   = (const int*)d_in[1];
    const int*   user_age = (const int*)d_in[2];
    const int*   gender   = (const int*)d_in[3];
    const int*   user_occ = (const int*)d_in[4];
    const int*   item_kind= (const int*)d_in[5];
    const int*   his_id   = (const int*)d_in[6];
    const int*   his_kind = (const int*)d_in[7];
    const float* user_emb = (const float*)d_in[8];
    const float* item_emb = (const float*)d_in[9];
    const float* age_emb  = (const float*)d_in[10];
    const float* gen_emb  = (const float*)d_in[11];
    const float* occ_emb  = (const float*)d_in[12];
    const float* kind_emb = (const float*)d_in[13];
    const float* act_w1 = (const float*)d_in[14];
    const float* act_b1 = (const float*)d_in[15];
    const float* act_w2 = (const float*)d_in[16];
    const float* act_b2 = (const float*)d_in[17];
    const float* act_w3 = (const float*)d_in[18];
    const float* act_b3 = (const float*)d_in[19];
    const float* mlp_w1 = (const float*)d_in[20];
    const float* mlp_b1 = (const float*)d_in[21];
    const float* mlp_w2 = (const float*)d_in[22];
    const float* mlp_b2 = (const float*)d_in[23];
    const float* mlp_w3 = (const float*)d_in[24];
    const float* mlp_b3 = (const float*)d_in[25];
    const float* mlp_w4 = (const float*)d_in[26];
    const float* mlp_b4 = (const float*)d_in[27];

    int B = in_sizes[0];
    int nb = (B + 127) / 128;

    cudaFuncSetAttribute((const void*)t2_mlp,
                         cudaFuncAttributeMaxDynamicSharedMemorySize, T2_SMEM);

    prep_tables<<<246, 256>>>(act_w1, mlp_w1, mlp_w2, mlp_w3, kind_emb);

    k0_feat<<<nb, 128>>>(userid, itemid, user_age, gender, user_occ, item_kind,
                         user_emb, item_emb, age_emb, gen_emb, occ_emb, kind_emb,
                         act_b1, B);

    k1s_score<<<nb, 128>>>(his_id, his_kind, item_emb, act_w1,
                           act_w2, act_b2, act_w3, act_b3, B);

    k2_pool<<<nb, 128>>>(his_id, his_kind, item_emb, kind_emb, B);

    t2_mlp<<<nb, 512, T2_SMEM>>>(mlp_b1, mlp_b2, mlp_b3, mlp_w4, mlp_b4,
                                 (float*)d_out, B);
}